// round 16
// baseline (speedup 1.0000x reference)
#include <cuda_runtime.h>
#include <cuda_fp16.h>
#include <math_constants.h>

#define BATCH 64
#define SEQ   256
#define TCH   16
#define VOC   262
#define EMB   64
#define HID   32
#define G3    96
#define NSEQ  (BATCH*SEQ)

// Tables (device globals — no allocation allowed)
// GI row (384B stride): floats [0..63] = r,z pre-acts (permuted
// pos = gate*32 + tig*8 + hg*2 + e, prescaled 0.5, bhh folded);
// bytes [256..320) = n pre-acts as 32 f16 (same permute, bih folded only).
__device__ __align__(128) float g_GI2[2 * VOC * G3];
// Pre-packed f16 B fragments (m16n8k16): [dir][nb][kc][lane] = uint2(b0,b1)
// nb<8 rows pre-scaled 0.5.
__device__ uint2 g_WF[2 * 12 * 2 * 32];

#define H05   0x38003800u    // f16x2 (0.5, 0.5)
#define HNINF 0xFC00FC00u    // f16x2 (-inf, -inf)

__device__ __forceinline__ unsigned pack2h(float lo, float hi) {
    unsigned d;
    asm("cvt.rn.f16x2.f32 %0, %1, %2;" : "=r"(d) : "f"(hi), "f"(lo));
    return d;
}
__device__ __forceinline__ unsigned tanh2(unsigned x) {
    unsigned d;
    asm("tanh.approx.f16x2 %0, %1;" : "=r"(d) : "r"(x));
    return d;
}
__device__ __forceinline__ unsigned fma2(unsigned a, unsigned b, unsigned c) {
    unsigned d;
    asm("fma.rn.f16x2 %0, %1, %2, %3;" : "=r"(d) : "r"(a), "r"(b), "r"(c));
    return d;
}
__device__ __forceinline__ unsigned sub2(unsigned a, unsigned b) {
    unsigned d;
    asm("sub.rn.f16x2 %0, %1, %2;" : "=r"(d) : "r"(a), "r"(b));
    return d;
}
__device__ __forceinline__ unsigned max2(unsigned a, unsigned b) {
    unsigned d;
    asm("max.f16x2 %0, %1, %2;" : "=r"(d) : "r"(a), "r"(b));
    return d;
}
// MMA accumulating IN-PLACE into four float lvalues (D == C registers)
__device__ __forceinline__ void mma4(float& d0, float& d1, float& d2, float& d3,
                                     const unsigned* a, unsigned b0, unsigned b1) {
    asm("mma.sync.aligned.m16n8k16.row.col.f32.f16.f16.f32 "
        "{%0,%1,%2,%3}, {%4,%5,%6,%7}, {%8,%9}, {%0,%1,%2,%3};"
        : "+f"(d0), "+f"(d1), "+f"(d2), "+f"(d3)
        : "r"(a[0]), "r"(a[1]), "r"(a[2]), "r"(a[3]), "r"(b0), "r"(b1));
}

// ---------------------------------------------------------------------------
// Kernel 1: GI tables (r,z f32 prescaled; n f16) + f16 B-fragment pack.
// grid = VOC+1, block = 192.  (unchanged from round 15)
// ---------------------------------------------------------------------------
__global__ void build_tables(const float* __restrict__ emb,
                             const float* __restrict__ Wih_f,
                             const float* __restrict__ bih_f,
                             const float* __restrict__ bhh_f,
                             const float* __restrict__ Wih_b,
                             const float* __restrict__ bih_b,
                             const float* __restrict__ bhh_b,
                             const float* __restrict__ Whh_f,
                             const float* __restrict__ Whh_b) {
    int c   = blockIdx.x;
    int tid = threadIdx.x;
    if (c < VOC) {
        int dir = tid / 96;
        int g   = tid % 96;
        __shared__ float e[EMB];
        if (tid < EMB) e[tid] = emb[c * EMB + tid];
        __syncthreads();
        const float* Wih = dir ? Wih_b : Wih_f;
        const float* bih = dir ? bih_b : bih_f;
        const float* bhh = dir ? bhh_b : bhh_f;
        float a0 = bih[g] + (g < 64 ? bhh[g] : 0.0f);
        float a1 = 0.0f;
        const float4* wr4 = (const float4*)(Wih + g * EMB);
        #pragma unroll
        for (int k4 = 0; k4 < EMB / 4; k4++) {
            float4 wv = wr4[k4];
            a0 = fmaf(wv.x, e[4 * k4],     a0);
            a1 = fmaf(wv.y, e[4 * k4 + 1], a1);
            a0 = fmaf(wv.z, e[4 * k4 + 2], a0);
            a1 = fmaf(wv.w, e[4 * k4 + 3], a1);
        }
        float v = a0 + a1;
        int j  = g & 31;
        int hg = j >> 3, tg = (j >> 1) & 3, eb = j & 1;
        int p  = tg * 8 + hg * 2 + eb;
        char* rowbase = (char*)g_GI2 + (dir * VOC + c) * (G3 * 4);
        if (g < 64) {
            int gate = g >> 5;
            ((float*)rowbase)[gate * 32 + p] = v * 0.5f;   // r,z prescaled
        } else {
            *(__half*)(rowbase + 256 + p * 2) = __float2half_rn(v);  // n, f16
        }
    } else {
        // pack f16 B fragments (2*12*2*32 = 1536 uint2)
        for (int i = tid; i < 1536; i += 192) {
            int d    = i / 768;
            int rem  = i % 768;
            int nb   = rem / 64;
            int kc   = (rem / 32) & 1;
            int lane = rem & 31;
            int gid = lane >> 2, tg = lane & 3;
            const float* W = d ? Whh_b : Whh_f;
            const float* row = W + (8 * nb + gid) * HID;
            float s = (nb < 8) ? 0.5f : 1.0f;    // r,z rows prescaled
            int k0 = 16 * kc + 2 * tg;
            g_WF[i] = make_uint2(pack2h(s * row[k0],     s * row[k0 + 1]),
                                 pack2h(s * row[k0 + 8], s * row[k0 + 9]));
        }
    }
}

// Per-task gi registers; doubles as the r/z MMA accumulators (in-place).
struct Gi {
    float4 ra0, ra1, za0, za1;   // rows A: r,z pre-acts (f32)
    float4 rb0, rb1, zb0, zb1;   // rows B
    uint4  nA, nB;               // n pre-acts (f16x2 packed)
};

__device__ __forceinline__ void load_gi(Gi& g, const float* __restrict__ GI,
                                        int cA, int cB, int tig) {
    const char* bA = (const char*)(GI + cA * G3);
    const char* bB = (const char*)(GI + cB * G3);
    g.ra0 = ((const float4*)bA)[tig * 2];
    g.ra1 = ((const float4*)bA)[tig * 2 + 1];
    g.za0 = ((const float4*)bA)[8 + tig * 2];
    g.za1 = ((const float4*)bA)[8 + tig * 2 + 1];
    g.nA  = *(const uint4*)(bA + 256 + tig * 16);
    g.rb0 = ((const float4*)bB)[tig * 2];
    g.rb1 = ((const float4*)bB)[tig * 2 + 1];
    g.zb0 = ((const float4*)bB)[8 + tig * 2];
    g.zb1 = ((const float4*)bB)[8 + tig * 2 + 1];
    g.nB  = *(const uint4*)(bB + 256 + tig * 16);
}

// dual-unit activation: r,z via sigmoid(x)=0.5+0.5*tanh(x/2) (prescaled)
__device__ __forceinline__ void act2(float xr0, float xr1, float xz0, float xz1,
                                     float ghn0, float ghn1, unsigned gin,
                                     unsigned& hpp, unsigned& hmm) {
    unsigned r2 = fma2(tanh2(pack2h(xr0, xr1)), H05, H05);
    unsigned z2 = fma2(tanh2(pack2h(xz0, xz1)), H05, H05);
    unsigned gh = pack2h(ghn0, ghn1);
    unsigned n2 = tanh2(fma2(r2, gh, gin));
    unsigned h2 = fma2(z2, sub2(hpp, n2), n2);
    hpp = h2;
    hmm = max2(hmm, h2);
}

// One GRU step for one task: MMAs accumulate in-place into g (r,z) and
// nacc (n); activations update hp/hm. g is DEAD on return (reload it).
__device__ __forceinline__ void gru_step(Gi& g, unsigned hp[4][2],
                                         unsigned hm[4][2],
                                         const float* bnlo, const float* bnhi,
                                         const unsigned bf[12][2][2]) {
    unsigned a0[4] = {hp[0][0], hp[0][1], hp[1][0], hp[1][1]};
    unsigned a1[4] = {hp[2][0], hp[2][1], hp[3][0], hp[3][1]};

    float nacc[4][4];
    #pragma unroll
    for (int hg = 0; hg < 4; hg++) {
        nacc[hg][0] = bnlo[hg]; nacc[hg][1] = bnhi[hg];
        nacc[hg][2] = bnlo[hg]; nacc[hg][3] = bnhi[hg];
    }

    // r tiles (nb 0..3), in-place into ra*/rb*
    mma4(g.ra0.x, g.ra0.y, g.rb0.x, g.rb0.y, a0, bf[0][0][0], bf[0][0][1]);
    mma4(g.ra0.x, g.ra0.y, g.rb0.x, g.rb0.y, a1, bf[0][1][0], bf[0][1][1]);
    mma4(g.ra0.z, g.ra0.w, g.rb0.z, g.rb0.w, a0, bf[1][0][0], bf[1][0][1]);
    mma4(g.ra0.z, g.ra0.w, g.rb0.z, g.rb0.w, a1, bf[1][1][0], bf[1][1][1]);
    mma4(g.ra1.x, g.ra1.y, g.rb1.x, g.rb1.y, a0, bf[2][0][0], bf[2][0][1]);
    mma4(g.ra1.x, g.ra1.y, g.rb1.x, g.rb1.y, a1, bf[2][1][0], bf[2][1][1]);
    mma4(g.ra1.z, g.ra1.w, g.rb1.z, g.rb1.w, a0, bf[3][0][0], bf[3][0][1]);
    mma4(g.ra1.z, g.ra1.w, g.rb1.z, g.rb1.w, a1, bf[3][1][0], bf[3][1][1]);
    // z tiles (nb 4..7)
    mma4(g.za0.x, g.za0.y, g.zb0.x, g.zb0.y, a0, bf[4][0][0], bf[4][0][1]);
    mma4(g.za0.x, g.za0.y, g.zb0.x, g.zb0.y, a1, bf[4][1][0], bf[4][1][1]);
    mma4(g.za0.z, g.za0.w, g.zb0.z, g.zb0.w, a0, bf[5][0][0], bf[5][0][1]);
    mma4(g.za0.z, g.za0.w, g.zb0.z, g.zb0.w, a1, bf[5][1][0], bf[5][1][1]);
    mma4(g.za1.x, g.za1.y, g.zb1.x, g.zb1.y, a0, bf[6][0][0], bf[6][0][1]);
    mma4(g.za1.x, g.za1.y, g.zb1.x, g.zb1.y, a1, bf[6][1][0], bf[6][1][1]);
    mma4(g.za1.z, g.za1.w, g.zb1.z, g.zb1.w, a0, bf[7][0][0], bf[7][0][1]);
    mma4(g.za1.z, g.za1.w, g.zb1.z, g.zb1.w, a1, bf[7][1][0], bf[7][1][1]);
    // n tiles (nb 8..11) into nacc
    #pragma unroll
    for (int m = 0; m < 4; m++) {
        mma4(nacc[m][0], nacc[m][1], nacc[m][2], nacc[m][3],
             a0, bf[8 + m][0][0], bf[8 + m][0][1]);
        mma4(nacc[m][0], nacc[m][1], nacc[m][2], nacc[m][3],
             a1, bf[8 + m][1][0], bf[8 + m][1][1]);
    }

    // activations: rows A then B
    act2(g.ra0.x, g.ra0.y, g.za0.x, g.za0.y, nacc[0][0], nacc[0][1], g.nA.x, hp[0][0], hm[0][0]);
    act2(g.ra0.z, g.ra0.w, g.za0.z, g.za0.w, nacc[1][0], nacc[1][1], g.nA.y, hp[1][0], hm[1][0]);
    act2(g.ra1.x, g.ra1.y, g.za1.x, g.za1.y, nacc[2][0], nacc[2][1], g.nA.z, hp[2][0], hm[2][0]);
    act2(g.ra1.z, g.ra1.w, g.za1.z, g.za1.w, nacc[3][0], nacc[3][1], g.nA.w, hp[3][0], hm[3][0]);
    act2(g.rb0.x, g.rb0.y, g.zb0.x, g.zb0.y, nacc[0][2], nacc[0][3], g.nB.x, hp[0][1], hm[0][1]);
    act2(g.rb0.z, g.rb0.w, g.zb0.z, g.zb0.w, nacc[1][2], nacc[1][3], g.nB.y, hp[1][1], hm[1][1]);
    act2(g.rb1.x, g.rb1.y, g.zb1.x, g.zb1.y, nacc[2][2], nacc[2][3], g.nB.z, hp[2][1], hm[2][1]);
    act2(g.rb1.z, g.rb1.w, g.zb1.z, g.zb1.w, nacc[3][2], nacc[3][3], g.nB.w, hp[3][1], hm[3][1]);
}

// ---------------------------------------------------------------------------
// Kernel 2: f16 tensor-core GRU with TWO INTERLEAVED tasks per warp.
// 512 blocks x 64 thr = 1024 warps; each warp advances two independent
// 16-seq GRUs in the same loop body — ptxas interleaves the chains, so one
// task's MMA issue hides the other's activation/memory latency.
// In-place accumulators: gi registers == MMA C/D; reloaded post-activation
// (the reload's L2 latency is covered by the other task's compute).
// ---------------------------------------------------------------------------
__global__ __launch_bounds__(64, 4)
void gru_mma(const int* __restrict__ x,
             const float* __restrict__ bhh_f,
             const float* __restrict__ bhh_b,
             float* __restrict__ out) {
    int tid  = threadIdx.x;
    int wb   = tid >> 5;
    int lane = tid & 31;
    int gid  = lane >> 2;
    int tig  = lane & 3;
    int dir  = blockIdx.x >> 8;                 // block-uniform
    int wi   = (blockIdx.x & 255) * 2 + wb;     // 0..511

    const float* __restrict__ GI  = g_GI2 + dir * (VOC * G3);
    const float* __restrict__ bhh = dir ? bhh_b : bhh_f;

    // B fragments in registers (f16x2), shared by both tasks
    unsigned bf[12][2][2];
    {
        const uint2* WF = g_WF + dir * 768;
        #pragma unroll
        for (int nb = 0; nb < 12; nb++)
            #pragma unroll
            for (int kc = 0; kc < 2; kc++) {
                uint2 v = WF[(nb * 2 + kc) * 32 + lane];
                bf[nb][kc][0] = v.x;
                bf[nb][kc][1] = v.y;
            }
    }
    float bnlo[4], bnhi[4];
    #pragma unroll
    for (int hg = 0; hg < 4; hg++) {
        bnlo[hg] = bhh[64 + 8 * hg + 2 * tig];
        bnhi[hg] = bhh[64 + 8 * hg + 2 * tig + 1];
    }

    int s0 = wi << 4;            // task 0 sequences
    int s1 = (wi + 512) << 4;    // task 1 sequences
    const int* xA0 = x + (s0 + gid) * TCH;
    const int* xB0 = x + (s0 + gid + 8) * TCH;
    const int* xA1 = x + (s1 + gid) * TCH;
    const int* xB1 = x + (s1 + gid + 8) * TCH;

    unsigned hp0[4][2], hm0[4][2], hp1[4][2], hm1[4][2];
    #pragma unroll
    for (int hg = 0; hg < 4; hg++) {
        hp0[hg][0] = 0u;    hp0[hg][1] = 0u;
        hm0[hg][0] = HNINF; hm0[hg][1] = HNINF;
        hp1[hg][0] = 0u;    hp1[hg][1] = 0u;
        hm1[hg][0] = HNINF; hm1[hg][1] = HNINF;
    }

    #define TIDX(k) (dir ? ((TCH - 1 - (k)) & (TCH - 1)) : ((k) & (TCH - 1)))

    Gi g0, g1;
    load_gi(g0, GI, xA0[TIDX(0)], xB0[TIDX(0)], tig);
    load_gi(g1, GI, xA1[TIDX(0)], xB1[TIDX(0)], tig);
    int cA0 = xA0[TIDX(1)], cB0 = xB0[TIDX(1)];
    int cA1 = xA1[TIDX(1)], cB1 = xB1[TIDX(1)];

    #pragma unroll 1
    for (int tt = 0; tt < TCH; ++tt) {
        int tn2 = TIDX(tt + 2);

        // task 0: compute step tt, then reload gi for tt+1
        gru_step(g0, hp0, hm0, bnlo, bnhi, bf);
        load_gi(g0, GI, cA0, cB0, tig);
        cA0 = xA0[tn2]; cB0 = xB0[tn2];

        // task 1: independent chain — interleaves with task 0's stalls
        gru_step(g1, hp1, hm1, bnlo, bnhi, bf);
        load_gi(g1, GI, cA1, cB1, tig);
        cA1 = xA1[tn2]; cB1 = xB1[tn2];
    }
    #undef TIDX

    #pragma unroll
    for (int hg = 0; hg < 4; hg++) {
        int col = 8 * hg + 2 * tig;
        *(float2*)(out + (s0 + gid)     * 64 + dir * 32 + col) = __half22float2(*(__half2*)&hm0[hg][0]);
        *(float2*)(out + (s0 + gid + 8) * 64 + dir * 32 + col) = __half22float2(*(__half2*)&hm0[hg][1]);
        *(float2*)(out + (s1 + gid)     * 64 + dir * 32 + col) = __half22float2(*(__half2*)&hm1[hg][0]);
        *(float2*)(out + (s1 + gid + 8) * 64 + dir * 32 + col) = __half22float2(*(__half2*)&hm1[hg][1]);
    }
}

// ---------------------------------------------------------------------------
// kernel_launch
// ---------------------------------------------------------------------------
extern "C" void kernel_launch(void* const* d_in, const int* in_sizes, int n_in,
                              void* d_out, int out_size) {
    const int*   x     = (const int*)  d_in[0];
    const float* emb   = (const float*)d_in[1];
    const float* Wih_f = (const float*)d_in[2];
    const float* Whh_f = (const float*)d_in[3];
    const float* bih_f = (const float*)d_in[4];
    const float* bhh_f = (const float*)d_in[5];
    const float* Wih_b = (const float*)d_in[6];
    const float* Whh_b = (const float*)d_in[7];
    const float* bih_b = (const float*)d_in[8];
    const float* bhh_b = (const float*)d_in[9];
    float* out = (float*)d_out;

    build_tables<<<VOC + 1, 192>>>(emb, Wih_f, bih_f, bhh_f,
                                   Wih_b, bih_b, bhh_b, Whh_f, Whh_b);

    // 512 blocks x 2 warps = 1024 warps; each warp runs TWO interleaved
    // 16-seq tasks. Blocks 0..255 dir0, 256..511 dir1. Single wave.
    gru_mma<<<512, 64>>>(x, bhh_f, bhh_b, out);
}

// round 17
// speedup vs baseline: 1.0010x; 1.0010x over previous
#include <cuda_runtime.h>
#include <cuda_fp16.h>
#include <math_constants.h>

#define BATCH 64
#define SEQ   256
#define TCH   16
#define VOC   262
#define EMB   64
#define HID   32
#define G3    96
#define NSEQ  (BATCH*SEQ)

// Tables (device globals — no allocation allowed)
// GI row (384B stride): floats [0..63] = r,z pre-acts (permuted
// pos = gate*32 + tig*8 + hg*2 + e, prescaled 0.5, bhh folded);
// bytes [256..320) = n pre-acts as 32 f16 (same permute, bih folded only).
__device__ __align__(128) float g_GI2[2 * VOC * G3];
// Pre-packed f16 B fragments (m16n8k16): [dir][nb][kc][lane] = uint2(b0,b1)
// nb<8 rows pre-scaled 0.5.
__device__ uint2 g_WF[2 * 12 * 2 * 32];

#define H05   0x38003800u    // f16x2 (0.5, 0.5)
#define HNINF 0xFC00FC00u    // f16x2 (-inf, -inf)

__device__ __forceinline__ unsigned pack2h(float lo, float hi) {
    unsigned d;
    asm("cvt.rn.f16x2.f32 %0, %1, %2;" : "=r"(d) : "f"(hi), "f"(lo));
    return d;
}
__device__ __forceinline__ unsigned tanh2(unsigned x) {
    unsigned d;
    asm("tanh.approx.f16x2 %0, %1;" : "=r"(d) : "r"(x));
    return d;
}
__device__ __forceinline__ unsigned fma2(unsigned a, unsigned b, unsigned c) {
    unsigned d;
    asm("fma.rn.f16x2 %0, %1, %2, %3;" : "=r"(d) : "r"(a), "r"(b), "r"(c));
    return d;
}
__device__ __forceinline__ unsigned sub2(unsigned a, unsigned b) {
    unsigned d;
    asm("sub.rn.f16x2 %0, %1, %2;" : "=r"(d) : "r"(a), "r"(b));
    return d;
}
__device__ __forceinline__ unsigned max2(unsigned a, unsigned b) {
    unsigned d;
    asm("max.f16x2 %0, %1, %2;" : "=r"(d) : "r"(a), "r"(b));
    return d;
}
// MMA accumulating IN-PLACE into four float lvalues (D == C registers)
__device__ __forceinline__ void mma4(float& d0, float& d1, float& d2, float& d3,
                                     const unsigned* a, unsigned b0, unsigned b1) {
    asm("mma.sync.aligned.m16n8k16.row.col.f32.f16.f16.f32 "
        "{%0,%1,%2,%3}, {%4,%5,%6,%7}, {%8,%9}, {%0,%1,%2,%3};"
        : "+f"(d0), "+f"(d1), "+f"(d2), "+f"(d3)
        : "r"(a[0]), "r"(a[1]), "r"(a[2]), "r"(a[3]), "r"(b0), "r"(b1));
}

// ---------------------------------------------------------------------------
// Kernel 1: GI tables (r,z f32 prescaled; n f16) + f16 B-fragment pack.
// grid = VOC+1, block = 192.
// ---------------------------------------------------------------------------
__global__ void build_tables(const float* __restrict__ emb,
                             const float* __restrict__ Wih_f,
                             const float* __restrict__ bih_f,
                             const float* __restrict__ bhh_f,
                             const float* __restrict__ Wih_b,
                             const float* __restrict__ bih_b,
                             const float* __restrict__ bhh_b,
                             const float* __restrict__ Whh_f,
                             const float* __restrict__ Whh_b) {
    int c   = blockIdx.x;
    int tid = threadIdx.x;
    if (c < VOC) {
        int dir = tid / 96;
        int g   = tid % 96;
        __shared__ float e[EMB];
        if (tid < EMB) e[tid] = emb[c * EMB + tid];
        __syncthreads();
        const float* Wih = dir ? Wih_b : Wih_f;
        const float* bih = dir ? bih_b : bih_f;
        const float* bhh = dir ? bhh_b : bhh_f;
        float a0 = bih[g] + (g < 64 ? bhh[g] : 0.0f);
        float a1 = 0.0f;
        const float4* wr4 = (const float4*)(Wih + g * EMB);
        #pragma unroll
        for (int k4 = 0; k4 < EMB / 4; k4++) {
            float4 wv = wr4[k4];
            a0 = fmaf(wv.x, e[4 * k4],     a0);
            a1 = fmaf(wv.y, e[4 * k4 + 1], a1);
            a0 = fmaf(wv.z, e[4 * k4 + 2], a0);
            a1 = fmaf(wv.w, e[4 * k4 + 3], a1);
        }
        float v = a0 + a1;
        int j  = g & 31;
        int hg = j >> 3, tg = (j >> 1) & 3, eb = j & 1;
        int p  = tg * 8 + hg * 2 + eb;
        char* rowbase = (char*)g_GI2 + (dir * VOC + c) * (G3 * 4);
        if (g < 64) {
            int gate = g >> 5;
            ((float*)rowbase)[gate * 32 + p] = v * 0.5f;   // r,z prescaled
        } else {
            *(__half*)(rowbase + 256 + p * 2) = __float2half_rn(v);  // n, f16
        }
    } else {
        // pack f16 B fragments (2*12*2*32 = 1536 uint2)
        for (int i = tid; i < 1536; i += 192) {
            int d    = i / 768;
            int rem  = i % 768;
            int nb   = rem / 64;
            int kc   = (rem / 32) & 1;
            int lane = rem & 31;
            int gid = lane >> 2, tg = lane & 3;
            const float* W = d ? Whh_b : Whh_f;
            const float* row = W + (8 * nb + gid) * HID;
            float s = (nb < 8) ? 0.5f : 1.0f;    // r,z rows prescaled
            int k0 = 16 * kc + 2 * tg;
            g_WF[i] = make_uint2(pack2h(s * row[k0],     s * row[k0 + 1]),
                                 pack2h(s * row[k0 + 8], s * row[k0 + 9]));
        }
    }
}

// Per-task gi registers; doubles as the r/z MMA accumulators (in-place).
struct Gi {
    float4 ra0, ra1, za0, za1;   // rows A: r,z pre-acts (f32)
    float4 rb0, rb1, zb0, zb1;   // rows B
    uint4  nA, nB;               // n pre-acts (f16x2 packed)
};

__device__ __forceinline__ void load_gi(Gi& g, const float* __restrict__ GI,
                                        int cA, int cB, int tig) {
    const char* bA = (const char*)(GI + cA * G3);
    const char* bB = (const char*)(GI + cB * G3);
    g.ra0 = ((const float4*)bA)[tig * 2];
    g.ra1 = ((const float4*)bA)[tig * 2 + 1];
    g.za0 = ((const float4*)bA)[8 + tig * 2];
    g.za1 = ((const float4*)bA)[8 + tig * 2 + 1];
    g.nA  = *(const uint4*)(bA + 256 + tig * 16);
    g.rb0 = ((const float4*)bB)[tig * 2];
    g.rb1 = ((const float4*)bB)[tig * 2 + 1];
    g.zb0 = ((const float4*)bB)[8 + tig * 2];
    g.zb1 = ((const float4*)bB)[8 + tig * 2 + 1];
    g.nB  = *(const uint4*)(bB + 256 + tig * 16);
}

// dual-unit activation: r,z via sigmoid(x)=0.5+0.5*tanh(x/2) (prescaled)
__device__ __forceinline__ void act2(float xr0, float xr1, float xz0, float xz1,
                                     float ghn0, float ghn1, unsigned gin,
                                     unsigned& hpp, unsigned& hmm) {
    unsigned r2 = fma2(tanh2(pack2h(xr0, xr1)), H05, H05);
    unsigned z2 = fma2(tanh2(pack2h(xz0, xz1)), H05, H05);
    unsigned gh = pack2h(ghn0, ghn1);
    unsigned n2 = tanh2(fma2(r2, gh, gin));
    unsigned h2 = fma2(z2, sub2(hpp, n2), n2);
    hpp = h2;
    hmm = max2(hmm, h2);
}

// One GRU step for one task: MMAs accumulate in-place into g (r,z) and
// nacc (n); B fragments come from shared memory. g is DEAD on return.
__device__ __forceinline__ void gru_step(Gi& g, unsigned hp[4][2],
                                         unsigned hm[4][2],
                                         const float* bnlo, const float* bnhi,
                                         const uint2* s_bf, int lane) {
    unsigned a0[4] = {hp[0][0], hp[0][1], hp[1][0], hp[1][1]};
    unsigned a1[4] = {hp[2][0], hp[2][1], hp[3][0], hp[3][1]};

    float nacc[4][4];
    #pragma unroll
    for (int hg = 0; hg < 4; hg++) {
        nacc[hg][0] = bnlo[hg]; nacc[hg][1] = bnhi[hg];
        nacc[hg][2] = bnlo[hg]; nacc[hg][3] = bnhi[hg];
    }

    #define BF(nb, kc) s_bf[((nb) * 2 + (kc)) * 32 + lane]
    // r tiles (nb 0..3), in-place into ra*/rb*
    { uint2 b = BF(0,0); mma4(g.ra0.x, g.ra0.y, g.rb0.x, g.rb0.y, a0, b.x, b.y); }
    { uint2 b = BF(0,1); mma4(g.ra0.x, g.ra0.y, g.rb0.x, g.rb0.y, a1, b.x, b.y); }
    { uint2 b = BF(1,0); mma4(g.ra0.z, g.ra0.w, g.rb0.z, g.rb0.w, a0, b.x, b.y); }
    { uint2 b = BF(1,1); mma4(g.ra0.z, g.ra0.w, g.rb0.z, g.rb0.w, a1, b.x, b.y); }
    { uint2 b = BF(2,0); mma4(g.ra1.x, g.ra1.y, g.rb1.x, g.rb1.y, a0, b.x, b.y); }
    { uint2 b = BF(2,1); mma4(g.ra1.x, g.ra1.y, g.rb1.x, g.rb1.y, a1, b.x, b.y); }
    { uint2 b = BF(3,0); mma4(g.ra1.z, g.ra1.w, g.rb1.z, g.rb1.w, a0, b.x, b.y); }
    { uint2 b = BF(3,1); mma4(g.ra1.z, g.ra1.w, g.rb1.z, g.rb1.w, a1, b.x, b.y); }
    // z tiles (nb 4..7)
    { uint2 b = BF(4,0); mma4(g.za0.x, g.za0.y, g.zb0.x, g.zb0.y, a0, b.x, b.y); }
    { uint2 b = BF(4,1); mma4(g.za0.x, g.za0.y, g.zb0.x, g.zb0.y, a1, b.x, b.y); }
    { uint2 b = BF(5,0); mma4(g.za0.z, g.za0.w, g.zb0.z, g.zb0.w, a0, b.x, b.y); }
    { uint2 b = BF(5,1); mma4(g.za0.z, g.za0.w, g.zb0.z, g.zb0.w, a1, b.x, b.y); }
    { uint2 b = BF(6,0); mma4(g.za1.x, g.za1.y, g.zb1.x, g.zb1.y, a0, b.x, b.y); }
    { uint2 b = BF(6,1); mma4(g.za1.x, g.za1.y, g.zb1.x, g.zb1.y, a1, b.x, b.y); }
    { uint2 b = BF(7,0); mma4(g.za1.z, g.za1.w, g.zb1.z, g.zb1.w, a0, b.x, b.y); }
    { uint2 b = BF(7,1); mma4(g.za1.z, g.za1.w, g.zb1.z, g.zb1.w, a1, b.x, b.y); }
    // n tiles (nb 8..11) into nacc
    #pragma unroll
    for (int m = 0; m < 4; m++) {
        { uint2 b = BF(8 + m, 0);
          mma4(nacc[m][0], nacc[m][1], nacc[m][2], nacc[m][3], a0, b.x, b.y); }
        { uint2 b = BF(8 + m, 1);
          mma4(nacc[m][0], nacc[m][1], nacc[m][2], nacc[m][3], a1, b.x, b.y); }
    }
    #undef BF

    // activations: rows A then B
    act2(g.ra0.x, g.ra0.y, g.za0.x, g.za0.y, nacc[0][0], nacc[0][1], g.nA.x, hp[0][0], hm[0][0]);
    act2(g.ra0.z, g.ra0.w, g.za0.z, g.za0.w, nacc[1][0], nacc[1][1], g.nA.y, hp[1][0], hm[1][0]);
    act2(g.ra1.x, g.ra1.y, g.za1.x, g.za1.y, nacc[2][0], nacc[2][1], g.nA.z, hp[2][0], hm[2][0]);
    act2(g.ra1.z, g.ra1.w, g.za1.z, g.za1.w, nacc[3][0], nacc[3][1], g.nA.w, hp[3][0], hm[3][0]);
    act2(g.rb0.x, g.rb0.y, g.zb0.x, g.zb0.y, nacc[0][2], nacc[0][3], g.nB.x, hp[0][1], hm[0][1]);
    act2(g.rb0.z, g.rb0.w, g.zb0.z, g.zb0.w, nacc[1][2], nacc[1][3], g.nB.y, hp[1][1], hm[1][1]);
    act2(g.rb1.x, g.rb1.y, g.zb1.x, g.zb1.y, nacc[2][2], nacc[2][3], g.nB.z, hp[2][1], hm[2][1]);
    act2(g.rb1.z, g.rb1.w, g.zb1.z, g.zb1.w, nacc[3][2], nacc[3][3], g.nB.w, hp[3][1], hm[3][1]);
}

// ---------------------------------------------------------------------------
// Kernel 2: f16 tensor-core GRU, TWO INTERLEAVED tasks per warp, B fragments
// in shared memory (frees 48 regs so the interleave fits WITHOUT hitting the
// 255-reg cap — the round-16 version spilled/serialized at regs=255).
// 512 blocks x 64 thr = 1024 warps; blocks dir-uniform (dir = blockIdx>>8).
// ---------------------------------------------------------------------------
__global__ __launch_bounds__(64, 4)
void gru_mma(const int* __restrict__ x,
             const float* __restrict__ bhh_f,
             const float* __restrict__ bhh_b,
             float* __restrict__ out) {
    __shared__ uint2 s_bf[12 * 2 * 32];     // 6 KB B fragments (dir-uniform)

    int tid  = threadIdx.x;
    int wb   = tid >> 5;
    int lane = tid & 31;
    int gid  = lane >> 2;
    int tig  = lane & 3;
    int dir  = blockIdx.x >> 8;                 // block-uniform
    int wi   = (blockIdx.x & 255) * 2 + wb;     // 0..511

    // copy this direction's B fragments to smem (coalesced, once per block)
    {
        const uint2* src = g_WF + dir * 768;
        #pragma unroll
        for (int i = 0; i < 12; i++)
            s_bf[tid + 64 * i] = src[tid + 64 * i];
    }
    __syncthreads();

    const float* __restrict__ GI  = g_GI2 + dir * (VOC * G3);
    const float* __restrict__ bhh = dir ? bhh_b : bhh_f;

    float bnlo[4], bnhi[4];
    #pragma unroll
    for (int hg = 0; hg < 4; hg++) {
        bnlo[hg] = bhh[64 + 8 * hg + 2 * tig];
        bnhi[hg] = bhh[64 + 8 * hg + 2 * tig + 1];
    }

    int s0 = wi << 4;            // task 0 sequences
    int s1 = (wi + 512) << 4;    // task 1 sequences
    const int* xA0 = x + (s0 + gid) * TCH;
    const int* xB0 = x + (s0 + gid + 8) * TCH;
    const int* xA1 = x + (s1 + gid) * TCH;
    const int* xB1 = x + (s1 + gid + 8) * TCH;

    unsigned hp0[4][2], hm0[4][2], hp1[4][2], hm1[4][2];
    #pragma unroll
    for (int hg = 0; hg < 4; hg++) {
        hp0[hg][0] = 0u;    hp0[hg][1] = 0u;
        hm0[hg][0] = HNINF; hm0[hg][1] = HNINF;
        hp1[hg][0] = 0u;    hp1[hg][1] = 0u;
        hm1[hg][0] = HNINF; hm1[hg][1] = HNINF;
    }

    #define TIDX(k) (dir ? ((TCH - 1 - (k)) & (TCH - 1)) : ((k) & (TCH - 1)))

    Gi g0, g1;
    load_gi(g0, GI, xA0[TIDX(0)], xB0[TIDX(0)], tig);
    load_gi(g1, GI, xA1[TIDX(0)], xB1[TIDX(0)], tig);
    int cA0 = xA0[TIDX(1)], cB0 = xB0[TIDX(1)];
    int cA1 = xA1[TIDX(1)], cB1 = xB1[TIDX(1)];

    #pragma unroll 1
    for (int tt = 0; tt < TCH; ++tt) {
        int tn2 = TIDX(tt + 2);

        // task 0: compute step tt, then reload gi for tt+1
        gru_step(g0, hp0, hm0, bnlo, bnhi, s_bf, lane);
        load_gi(g0, GI, cA0, cB0, tig);
        cA0 = xA0[tn2]; cB0 = xB0[tn2];

        // task 1: independent chain — interleaves with task 0's stalls
        gru_step(g1, hp1, hm1, bnlo, bnhi, s_bf, lane);
        load_gi(g1, GI, cA1, cB1, tig);
        cA1 = xA1[tn2]; cB1 = xB1[tn2];
    }
    #undef TIDX

    #pragma unroll
    for (int hg = 0; hg < 4; hg++) {
        int col = 8 * hg + 2 * tig;
        *(float2*)(out + (s0 + gid)     * 64 + dir * 32 + col) = __half22float2(*(__half2*)&hm0[hg][0]);
        *(float2*)(out + (s0 + gid + 8) * 64 + dir * 32 + col) = __half22float2(*(__half2*)&hm0[hg][1]);
        *(float2*)(out + (s1 + gid)     * 64 + dir * 32 + col) = __half22float2(*(__half2*)&hm1[hg][0]);
        *(float2*)(out + (s1 + gid + 8) * 64 + dir * 32 + col) = __half22float2(*(__half2*)&hm1[hg][1]);
    }
}

// ---------------------------------------------------------------------------
// kernel_launch
// ---------------------------------------------------------------------------
extern "C" void kernel_launch(void* const* d_in, const int* in_sizes, int n_in,
                              void* d_out, int out_size) {
    const int*   x     = (const int*)  d_in[0];
    const float* emb   = (const float*)d_in[1];
    const float* Wih_f = (const float*)d_in[2];
    const float* Whh_f = (const float*)d_in[3];
    const float* bih_f = (const float*)d_in[4];
    const float* bhh_f = (const float*)d_in[5];
    const float* Wih_b = (const float*)d_in[6];
    const float* Whh_b = (const float*)d_in[7];
    const float* bih_b = (const float*)d_in[8];
    const float* bhh_b = (const float*)d_in[9];
    float* out = (float*)d_out;

    build_tables<<<VOC + 1, 192>>>(emb, Wih_f, bih_f, bhh_f,
                                   Wih_b, bih_b, bhh_b, Whh_f, Whh_b);

    // 512 blocks x 2 warps = 1024 warps; each warp runs TWO interleaved
    // 16-seq tasks. Blocks 0..255 dir0, 256..511 dir1. Single wave.
    gru_mma<<<512, 64>>>(x, bhh_f, bhh_b, out);
}